// round 4
// baseline (speedup 1.0000x reference)
#include <cuda_runtime.h>

// KVCache append — persistent single-wave kernel.
// B=4,H=32,S=4096,T=1,D=128 fp32.
// out = [k_cache ++ k_val (axis=2)] then [v_cache ++ v_val].
// 1.074GB streaming traffic. One wave of 1184 blocks (148 SM x 8 blocks,
// 2048 thr/SM) grid-strides over 1024-float4 chunks: no wave transitions,
// no dispatch ramp. All index math is shifts (everything power-of-2).

#define KV_S 4096
#define KV_T 1
#define KV_D 128

#define ROWS         128                          // B*H
#define ROW4_IN      (KV_S * KV_D / 4)            // 131072 = 2^17 float4/row
#define ROW4_OUT     ((KV_S + KV_T) * KV_D / 4)   // 131104 float4/row (out)
#define HALF4        ((long)ROWS * ROW4_OUT)      // float4 per output tensor
#define VAL4_PER_ROW (KV_T * KV_D / 4)            // 32 float4 per row append

#define UNROLL   4
#define TPB      256
#define CHUNK    (TPB * UNROLL)                   // 1024 float4 per chunk
#define CACHE4   (2L * ROWS * ROW4_IN)            // 33554432 float4 total
#define NCHUNKS  ((int)(CACHE4 / CHUNK))          // 32768 chunks
#define GRID     (148 * 8)                        // 1184: one full wave
#define VAL4_TOT (2 * ROWS * VAL4_PER_ROW)        // 8192 float4

__global__ void __launch_bounds__(TPB)
kv_append(const float4* __restrict__ k_cache,
          const float4* __restrict__ v_cache,
          const float4* __restrict__ k_val,
          const float4* __restrict__ v_val,
          float4* __restrict__ out)
{
    // --- tiny val append: first 32 blocks, one 256-thread slice each ---
    if (blockIdx.x < VAL4_TOT / TPB) {
        const int idx  = blockIdx.x * TPB + threadIdx.x;   // 0..8191
        const int half = idx >> 12;                        // /4096
        const int row  = (idx >> 5) & (ROWS - 1);
        const int d4   = idx & (VAL4_PER_ROW - 1);
        const float4* __restrict__ sv = half ? v_val : k_val;
        __stcs(&out[(long)half * HALF4 + (long)row * ROW4_OUT + ROW4_IN + d4],
               __ldcs(&sv[row * VAL4_PER_ROW + d4]));
    }

    // --- bulk cache copy: persistent grid-stride over chunks ---
    for (int c = blockIdx.x; c < NCHUNKS; c += GRID) {
        const long base = (long)c * CHUNK + threadIdx.x;   // linear float4 idx
        // virtual layout: [half(1b)][row(7b)][off(17b)]
        const int  half = (int)(base >> 24);
        const int  row  = (int)(base >> 17) & (ROWS - 1);
        const long off  = base & (ROW4_IN - 1);

        const float4* __restrict__ src =
            (half ? v_cache : k_cache) + ((long)row << 17) + off;
        float4* __restrict__ dst =
            out + (long)half * HALF4 + (long)row * ROW4_OUT + off;

        // within a chunk, base+u*TPB stays inside the same row (CHUNK | 2^17)
        float4 r[UNROLL];
        #pragma unroll
        for (int u = 0; u < UNROLL; u++)
            r[u] = __ldcs(&src[u * TPB]);
        #pragma unroll
        for (int u = 0; u < UNROLL; u++)
            __stcs(&dst[u * TPB], r[u]);
    }
}

extern "C" void kernel_launch(void* const* d_in, const int* in_sizes, int n_in,
                              void* d_out, int out_size)
{
    const float4* k_cache = (const float4*)d_in[0];
    const float4* v_cache = (const float4*)d_in[1];
    const float4* k_val   = (const float4*)d_in[2];
    const float4* v_val   = (const float4*)d_in[3];
    float4* out = (float4*)d_out;

    kv_append<<<GRID, TPB>>>(k_cache, v_cache, k_val, v_val, out);
}

// round 5
// speedup vs baseline: 1.1167x; 1.1167x over previous
#include <cuda_runtime.h>

// KVCache append — fused single kernel, R2-optimal launch shape.
// B=4,H=32,S=4096,T=1,D=128 fp32.
// out = [k_cache ++ k_val (axis=2)] then [v_cache ++ v_val].
// 537MB in + 537MB out pure stream; measured ceiling ~6.84TB/s (LTS cap).
// One-shot blocks (no grid-stride loop: persistent variant measured -9%),
// UNROLL=4 float4 per thread, streaming cache hints. Val append is folded
// into warp 0 of the x==0 block of each (row, half) — zero extra blocks.

#define KV_S 4096
#define KV_T 1
#define KV_D 128

#define ROWS         128                         // B*H rows
#define ROW4_IN      (KV_S * KV_D / 4)           // 131072 float4 per cache row
#define ROW4_OUT     ((KV_S + KV_T) * KV_D / 4)  // 131104 float4 per output row
#define HALF4        ((long)ROWS * ROW4_OUT)     // float4 per output tensor
#define VAL4_PER_ROW (KV_T * KV_D / 4)           // 32 float4 appended per row

#define UNROLL     4
#define TPB        256
#define CHUNK      (TPB * UNROLL)                // 1024 float4 per block
#define CACHE_BLKS (ROW4_IN / CHUNK)             // 128 x-blocks per (row,half)

__global__ void __launch_bounds__(TPB)
kv_append(const float4* __restrict__ k_cache,
          const float4* __restrict__ v_cache,
          const float4* __restrict__ k_val,
          const float4* __restrict__ v_val,
          float4* __restrict__ out)
{
    const int half = blockIdx.z;   // 0 = k, 1 = v
    const int row  = blockIdx.y;   // (b,h) flattened

    float4* __restrict__ dst = out + (long)half * HALF4 + (long)row * ROW4_OUT;

    // Fused token append: first warp of the x==0 block writes the 32 float4
    // (512B) new-token slot for this (row, half).
    if (blockIdx.x == 0 && threadIdx.x < VAL4_PER_ROW) {
        const float4* __restrict__ sv = half ? v_val : k_val;
        __stcs(&dst[ROW4_IN + threadIdx.x],
               __ldcs(&sv[row * VAL4_PER_ROW + threadIdx.x]));
    }

    // Bulk cache copy: 4 coalesced float4 per thread, loads batched before
    // stores for clean read/write bursts.
    const float4* __restrict__ src =
        (half ? v_cache : k_cache) + (long)row * ROW4_IN;
    const long base = (long)blockIdx.x * CHUNK + threadIdx.x;

    float4 r[UNROLL];
    #pragma unroll
    for (int u = 0; u < UNROLL; u++)
        r[u] = __ldcs(&src[base + u * TPB]);
    #pragma unroll
    for (int u = 0; u < UNROLL; u++)
        __stcs(&dst[base + u * TPB], r[u]);
}

extern "C" void kernel_launch(void* const* d_in, const int* in_sizes, int n_in,
                              void* d_out, int out_size)
{
    const float4* k_cache = (const float4*)d_in[0];
    const float4* v_cache = (const float4*)d_in[1];
    const float4* k_val   = (const float4*)d_in[2];
    const float4* v_val   = (const float4*)d_in[3];
    float4* out = (float4*)d_out;

    dim3 grid(CACHE_BLKS, ROWS, 2);  // (128, 128, 2) = 32768 full-work blocks
    kv_append<<<grid, TPB>>>(k_cache, v_cache, k_val, v_val, out);
}